// round 5
// baseline (speedup 1.0000x reference)
#include <cuda_runtime.h>
#include <math.h>

// ---------------- problem constants ----------------
#define Bv    32
#define Himg  56
#define Wimg  56
#define Cdim  256
#define WS    7
#define NHh   8
#define HDd   32
#define KCH   16
#define KSPT  28
#define Ntok  49
#define NWb   64              // windows per image (8*8)
#define BW    (Bv*NWb)        // 2048
#define BNh   (BW*NHh)        // 16384
#define Mrows (BW*Ntok)       // 100352
#define MLPH  1024
#define QK_SCALE 0.17677669529663687f

// ---------------- scratch (device globals; no allocs allowed) ----------------
__device__ float g_xw [Mrows*Cdim];
__device__ float g_q  [Mrows*Cdim];
__device__ float g_qc [Mrows*(Cdim/2)];
__device__ float g_k  [Mrows*(Cdim/2)];
__device__ float g_vin[BW*KSPT*Cdim];
__device__ float g_vp [BW*KSPT*Cdim];
__device__ float g_o  [Mrows*Cdim];
__device__ float g_xr [Mrows*Cdim];
__device__ float g_x2 [Mrows*Cdim];
__device__ float g_hb [Mrows*MLPH];
__device__ int   g_cidx[BNh*KCH];
__device__ int   g_sidx[BNh*KSPT];

__device__ __forceinline__ float gelu_f(float v) {
    return 0.5f * v * (1.0f + erff(v * 0.7071067811865476f));
}

// ---------------- LayerNorm (one block = one row of 256) ----------------
// mode 0: write window-partitioned; mode 1: identity row mapping
template<int MODE>
__global__ void ln_kernel(const float* __restrict__ x, const float* __restrict__ g,
                          const float* __restrict__ b, float* __restrict__ out)
{
    int r = blockIdx.x;
    int tid = threadIdx.x;
    float v = x[(size_t)r*Cdim + tid];
    float s = v, sq = v*v;
    __shared__ float ws[8], wq[8];
    #pragma unroll
    for (int o = 16; o > 0; o >>= 1) {
        s  += __shfl_down_sync(0xffffffffu, s,  o);
        sq += __shfl_down_sync(0xffffffffu, sq, o);
    }
    if ((tid & 31) == 0) { ws[tid >> 5] = s; wq[tid >> 5] = sq; }
    __syncthreads();
    float ts = 0.f, tq = 0.f;
    #pragma unroll
    for (int i = 0; i < 8; i++) { ts += ws[i]; tq += wq[i]; }
    float mean = ts * (1.0f/Cdim);
    float var  = tq * (1.0f/Cdim) - mean*mean;
    float rstd = rsqrtf(var + 1e-5f);
    float y = (v - mean) * rstd * g[tid] + b[tid];

    int dst;
    if (MODE == 0) {
        int bimg = r / (Himg*Wimg);
        int l    = r % (Himg*Wimg);
        int hr = l / Wimg, wc = l % Wimg;
        int wh = hr / WS, iwh = hr % WS;
        int ww = wc / WS, iww = wc % WS;
        dst = ((bimg*NWb + wh*8 + ww) * Ntok) + iwh*WS + iww;
    } else {
        dst = r;
    }
    out[(size_t)dst*Cdim + tid] = y;
}

// ---------------- SGEMM 64x64x16, 256 thr, 4x4 per thread ----------------
// EPI: 0 = +bias; 1 = gelu(+bias); 2 = +bias + res[row]; 3 = +bias + res[remapped row] (window reverse)
template<int EPI>
__global__ void sgemm64(const float* __restrict__ A, const float* __restrict__ Bm,
                        const float* __restrict__ bias, float* __restrict__ C,
                        int M, int N, int K, const float* __restrict__ res)
{
    __shared__ float As[16][64];
    __shared__ float Bs[16][64];
    int bm = blockIdx.y * 64;
    int bn = blockIdx.x * 64;
    int tid = threadIdx.x;
    int tx = tid & 15, ty = tid >> 4;
    float acc[4][4] = {};
    for (int k0 = 0; k0 < K; k0 += 16) {
        #pragma unroll
        for (int i = 0; i < 4; i++) {
            int p = tid + i*256;
            int m = p >> 4, kk = p & 15;
            As[kk][m] = A[(size_t)(bm+m)*K + k0 + kk];
        }
        #pragma unroll
        for (int i = 0; i < 4; i++) {
            int p = tid + i*256;
            int kk = p >> 6, n = p & 63;
            Bs[kk][n] = Bm[(size_t)(k0+kk)*N + bn + n];
        }
        __syncthreads();
        #pragma unroll
        for (int kk = 0; kk < 16; kk++) {
            float a[4], bb[4];
            #pragma unroll
            for (int i = 0; i < 4; i++) a[i]  = As[kk][ty*4+i];
            #pragma unroll
            for (int j = 0; j < 4; j++) bb[j] = Bs[kk][tx*4+j];
            #pragma unroll
            for (int i = 0; i < 4; i++)
                #pragma unroll
                for (int j = 0; j < 4; j++)
                    acc[i][j] += a[i]*bb[j];
        }
        __syncthreads();
    }
    #pragma unroll
    for (int i = 0; i < 4; i++) {
        int m = bm + ty*4 + i;
        int outrow = m;
        if (EPI == 3) {
            int bw = m / Ntok, nt = m % Ntok;
            int bimg = bw >> 6, rem = bw & 63;
            int wh = rem >> 3, ww = rem & 7;
            int hr = wh*WS + nt/WS;
            int wc = ww*WS + nt%WS;
            outrow = bimg*(Himg*Wimg) + hr*Wimg + wc;
        }
        #pragma unroll
        for (int j = 0; j < 4; j++) {
            int n = bn + tx*4 + j;
            float v = acc[i][j] + bias[n];
            if (EPI == 1) v = gelu_f(v);
            if (EPI == 2) v += res[(size_t)m*N + n];
            if (EPI == 3) v += res[(size_t)outrow*N + n];
            C[(size_t)outrow*N + n] = v;
        }
    }
}

// ---------------- channel + spatial top-k (one block per head-window) ----------------
__global__ void topk_kernel(const float* __restrict__ wch, const float* __restrict__ bch)
{
    int bn = blockIdx.x;
    int bw = bn >> 3, hh = bn & 7;
    int tid = threadIdx.x;  // 64 threads
    __shared__ float sh[Ntok*33];
    __shared__ float feat[2*HDd];
    __shared__ float sp[HDd];
    __shared__ float tm[Ntok];
    __shared__ int   selflag[Ntok];

    for (int e = tid; e < Ntok*HDd; e += 64) {
        int n = e >> 5, d = e & 31;
        sh[n*33 + d] = g_q[((size_t)bw*Ntok + n)*Cdim + hh*HDd + d];
    }
    __syncthreads();

    if (tid < HDd) {
        float m = 0.f, mx = -1e30f;
        #pragma unroll 7
        for (int n = 0; n < Ntok; n++) {
            float v = sh[n*33 + tid];
            m += v; mx = fmaxf(mx, v);
        }
        feat[tid] = m * (1.0f/Ntok);
        feat[HDd + tid] = mx;
    }
    __syncthreads();

    if (tid < HDd) {
        float s = bch[tid];
        #pragma unroll 8
        for (int i = 0; i < 2*HDd; i++) s += feat[i]*wch[i*HDd + tid];
        sp[tid] = gelu_f(s);   // softmax is monotone per row; rank on gelu output is identical
    }
    __syncthreads();

    if (tid < HDd) {
        float v = sp[tid];
        int rank = 0;
        #pragma unroll 8
        for (int i = 0; i < HDd; i++) {
            float u = sp[i];
            rank += (u > v) || (u == v && i < tid);
        }
        bool sel = rank < KCH;
        unsigned mask = __ballot_sync(0xffffffffu, sel);
        if (sel) {
            int pos = __popc(mask & ((1u << tid) - 1));
            g_cidx[bn*KCH + pos] = tid;
        }
    }

    // spatial top-k by token mean (sum is monotone vs mean)
    if (tid < Ntok) {
        float m = 0.f;
        #pragma unroll 8
        for (int d = 0; d < HDd; d++) m += sh[tid*33 + d];
        tm[tid] = m;
    }
    __syncthreads();
    if (tid < Ntok) {
        float v = tm[tid];
        int rank = 0;
        for (int i = 0; i < Ntok; i++) {
            float u = tm[i];
            rank += (u > v) || (u == v && i < tid);
        }
        selflag[tid] = (rank < KSPT) ? 1 : 0;
    }
    __syncthreads();
    if (tid < Ntok && selflag[tid]) {
        int pos = 0;
        for (int i = 0; i < tid; i++) pos += selflag[i];
        g_sidx[bn*KSPT + pos] = tid;
    }
}

// ---------------- gathers ----------------
__global__ void gather_qcha_kernel()
{
    int i = blockIdx.x * blockDim.x + threadIdx.x;   // Mrows*128 elements
    if (i >= Mrows*(Cdim/2)) return;
    int j  = i & 15;
    int t  = i >> 4;
    int hh = t & 7;
    int rn = t >> 3;
    int n  = rn % Ntok;
    int bw = rn / Ntok;
    int c  = g_cidx[(bw*NHh + hh)*KCH + j];
    g_qc[((size_t)bw*Ntok + n)*(Cdim/2) + hh*KCH + j] =
        g_q[((size_t)bw*Ntok + n)*Cdim + hh*HDd + c];
}

__global__ void gather_vin_kernel()
{
    int i = blockIdx.x * blockDim.x + threadIdx.x;   // BW*KSPT*256 elements
    if (i >= BW*KSPT*Cdim) return;
    int d  = i & 31;
    int u  = i >> 5;
    int hh = u & 7;
    int w  = u >> 3;
    int t  = w % KSPT;
    int bw = w / KSPT;
    int n  = g_sidx[(bw*NHh + hh)*KSPT + t];
    g_vin[((size_t)bw*KSPT + t)*Cdim + hh*HDd + d] =
        g_q[((size_t)bw*Ntok + n)*Cdim + hh*HDd + d];
}

// ---------------- attention core (one block per window-head) ----------------
__global__ void attn_kernel(const float* __restrict__ rpb_table)
{
    int bw = blockIdx.x >> 3;
    int hh = blockIdx.x & 7;
    int bn = blockIdx.x;
    int tid = threadIdx.x;   // 128 threads

    __shared__ float s_k[Ntok][KCH];
    __shared__ float s_q[KSPT][KCH];
    __shared__ float s_v[KSPT][HDd];
    __shared__ float s_at[Ntok][KSPT];
    __shared__ int   s_si[KSPT];

    if (tid < KSPT) s_si[tid] = g_sidx[bn*KSPT + tid];
    __syncthreads();

    for (int e = tid; e < Ntok*KCH; e += 128) {
        int n = e >> 4, j = e & 15;
        s_k[n][j] = g_k[((size_t)bw*Ntok + n)*(Cdim/2) + hh*KCH + j];
    }
    for (int e = tid; e < KSPT*KCH; e += 128) {
        int t = e >> 4, j = e & 15;
        s_q[t][j] = g_qc[((size_t)bw*Ntok + s_si[t])*(Cdim/2) + hh*KCH + j] * QK_SCALE;
    }
    for (int e = tid; e < KSPT*HDd; e += 128) {
        int t = e >> 5, d = e & 31;
        s_v[t][d] = g_vp[((size_t)bw*KSPT + t)*Cdim + hh*HDd + d];
    }
    __syncthreads();

    for (int e = tid; e < Ntok*KSPT; e += 128) {
        int n = e / KSPT, t = e % KSPT;
        float s = 0.f;
        #pragma unroll
        for (int j = 0; j < KCH; j++) s += s_k[n][j]*s_q[t][j];
        int m = s_si[t];
        int di0 = n/WS - m/WS + (WS-1);
        int di1 = n%WS - m%WS + (WS-1);
        s += rpb_table[(di0*(2*WS-1) + di1)*NHh + hh];
        s_at[n][t] = s;
    }
    __syncthreads();

    if (tid < Ntok) {
        float mean = 0.f, mx = -1e30f;
        #pragma unroll
        for (int t = 0; t < KSPT; t++) {
            float v = s_at[tid][t];
            mean += v; mx = fmaxf(mx, v);
        }
        mean *= (1.0f/KSPT);
        float gate = 1.0f / (1.0f + expf(-mean));
        float sum = 0.f;
        #pragma unroll
        for (int t = 0; t < KSPT; t++) {
            float e = expf(s_at[tid][t] - mx);
            s_at[tid][t] = e; sum += e;
        }
        float sc = gate / sum;
        #pragma unroll
        for (int t = 0; t < KSPT; t++) s_at[tid][t] *= sc;
    }
    __syncthreads();

    for (int e = tid; e < Ntok*HDd; e += 128) {
        int n = e >> 5, d = e & 31;
        float s = 0.f;
        #pragma unroll
        for (int t = 0; t < KSPT; t++) s += s_at[n][t]*s_v[t][d];
        g_o[((size_t)bw*Ntok + n)*Cdim + hh*HDd + d] = s;
    }
}

// ---------------- launch ----------------
extern "C" void kernel_launch(void* const* d_in, const int* in_sizes, int n_in,
                              void* d_out, int out_size)
{
    const float* x       = (const float*)d_in[0];
    const float* norm1_g = (const float*)d_in[1];
    const float* norm1_b = (const float*)d_in[2];
    const float* wq      = (const float*)d_in[3];
    const float* bq      = (const float*)d_in[4];
    const float* wk      = (const float*)d_in[5];
    const float* bk      = (const float*)d_in[6];
    const float* wv      = (const float*)d_in[7];
    const float* bv      = (const float*)d_in[8];
    const float* wproj   = (const float*)d_in[9];
    const float* bproj   = (const float*)d_in[10];
    const float* wch     = (const float*)d_in[11];
    const float* bch     = (const float*)d_in[12];
    const float* rpb     = (const float*)d_in[13];
    const float* norm2_g = (const float*)d_in[14];
    const float* norm2_b = (const float*)d_in[15];
    const float* w1      = (const float*)d_in[16];
    const float* b1      = (const float*)d_in[17];
    const float* w2      = (const float*)d_in[18];
    const float* b2      = (const float*)d_in[19];
    float* out = (float*)d_out;

    float *xw, *q, *qc, *kk, *vin, *vp, *oo, *xr, *x2, *hb;
    cudaGetSymbolAddress((void**)&xw, g_xw);
    cudaGetSymbolAddress((void**)&q,  g_q);
    cudaGetSymbolAddress((void**)&qc, g_qc);
    cudaGetSymbolAddress((void**)&kk, g_k);
    cudaGetSymbolAddress((void**)&vin,g_vin);
    cudaGetSymbolAddress((void**)&vp, g_vp);
    cudaGetSymbolAddress((void**)&oo, g_o);
    cudaGetSymbolAddress((void**)&xr, g_xr);
    cudaGetSymbolAddress((void**)&x2, g_x2);
    cudaGetSymbolAddress((void**)&hb, g_hb);

    // 1. LN1 + window partition
    ln_kernel<0><<<Mrows, 256>>>(x, norm1_g, norm1_b, xw);

    // 2. Q = xw @ wq + bq
    sgemm64<0><<<dim3(Cdim/64, Mrows/64), 256>>>(xw, wq, bq, q, Mrows, Cdim, Cdim, nullptr);

    // 3. channel + spatial top-k
    topk_kernel<<<BNh, 64>>>(wch, bch);

    // 4/5. gathers
    gather_qcha_kernel<<<(Mrows*(Cdim/2)+255)/256, 256>>>();
    gather_vin_kernel<<<(BW*KSPT*Cdim+255)/256, 256>>>();

    // 6. K = qcha1 @ wk + bk
    sgemm64<0><<<dim3((Cdim/2)/64, Mrows/64), 256>>>(qc, wk, bk, kk, Mrows, Cdim/2, Cdim/2, nullptr);

    // 7. V = vin @ wv + bv
    sgemm64<0><<<dim3(Cdim/64, (BW*KSPT)/64), 256>>>(vin, wv, bv, vp, BW*KSPT, Cdim, Cdim, nullptr);

    // 8. attention
    attn_kernel<<<BNh, 128>>>(rpb);

    // 9. out-proj + window reverse + shortcut  -> xr
    sgemm64<3><<<dim3(Cdim/64, Mrows/64), 256>>>(oo, wproj, bproj, xr, Mrows, Cdim, Cdim, x);

    // 10. LN2
    ln_kernel<1><<<Mrows, 256>>>(xr, norm2_g, norm2_b, x2);

    // 11. h = gelu(x2 @ w1 + b1)
    sgemm64<1><<<dim3(MLPH/64, Mrows/64), 256>>>(x2, w1, b1, hb, Mrows, MLPH, Cdim, nullptr);

    // 12. out = xr + h @ w2 + b2
    sgemm64<2><<<dim3(Cdim/64, Mrows/64), 256>>>(hb, w2, b2, out, Mrows, Cdim, MLPH, xr);
}

// round 6
// speedup vs baseline: 2.1810x; 2.1810x over previous
#include <cuda_runtime.h>
#include <math.h>

// ---------------- problem constants ----------------
#define Bv    32
#define Himg  56
#define Wimg  56
#define Cdim  256
#define WS    7
#define NHh   8
#define HDd   32
#define KCH   16
#define KSPT  28
#define Ntok  49
#define NWb   64              // windows per image (8*8)
#define BW    (Bv*NWb)        // 2048
#define BNh   (BW*NHh)        // 16384
#define Mrows (BW*Ntok)       // 100352
#define MLPH  1024
#define QK_SCALE 0.17677669529663687f

// ---------------- scratch (device globals; no allocs allowed) ----------------
__device__ float g_xw [Mrows*Cdim];
__device__ float g_q  [Mrows*Cdim];
__device__ float g_qc [Mrows*(Cdim/2)];
__device__ float g_k  [Mrows*(Cdim/2)];
__device__ float g_vin[BW*KSPT*Cdim];
__device__ float g_vp [BW*KSPT*Cdim];
__device__ float g_o  [Mrows*Cdim];
__device__ float g_xr [Mrows*Cdim];
__device__ float g_x2 [Mrows*Cdim];
__device__ float g_hb [Mrows*MLPH];
__device__ int   g_cidx[BNh*KCH];
__device__ int   g_sidx[BNh*KSPT];

__device__ __forceinline__ float gelu_f(float v) {
    return 0.5f * v * (1.0f + erff(v * 0.7071067811865476f));
}

__device__ __forceinline__ unsigned f2tf(float f) {
    unsigned u;
    asm("cvt.rna.tf32.f32 %0, %1;" : "=r"(u) : "f"(f));
    return u;
}

// ---------------- LayerNorm (one block = one row of 256) ----------------
template<int MODE>
__global__ void ln_kernel(const float* __restrict__ x, const float* __restrict__ g,
                          const float* __restrict__ b, float* __restrict__ out)
{
    int r = blockIdx.x;
    int tid = threadIdx.x;
    float v = x[(size_t)r*Cdim + tid];
    float s = v, sq = v*v;
    __shared__ float ws[8], wq[8];
    #pragma unroll
    for (int o = 16; o > 0; o >>= 1) {
        s  += __shfl_down_sync(0xffffffffu, s,  o);
        sq += __shfl_down_sync(0xffffffffu, sq, o);
    }
    if ((tid & 31) == 0) { ws[tid >> 5] = s; wq[tid >> 5] = sq; }
    __syncthreads();
    float ts = 0.f, tq = 0.f;
    #pragma unroll
    for (int i = 0; i < 8; i++) { ts += ws[i]; tq += wq[i]; }
    float mean = ts * (1.0f/Cdim);
    float var  = tq * (1.0f/Cdim) - mean*mean;
    float rstd = rsqrtf(var + 1e-5f);
    float y = (v - mean) * rstd * g[tid] + b[tid];

    int dst;
    if (MODE == 0) {
        int bimg = r / (Himg*Wimg);
        int l    = r % (Himg*Wimg);
        int hr = l / Wimg, wc = l % Wimg;
        int wh = hr / WS, iwh = hr % WS;
        int ww = wc / WS, iww = wc % WS;
        dst = ((bimg*NWb + wh*8 + ww) * Ntok) + iwh*WS + iww;
    } else {
        dst = r;
    }
    out[(size_t)dst*Cdim + tid] = y;
}

// ---------------- exact fp32 SGEMM (used ONLY for Q: feeds top-k ranking) ----
template<int EPI>
__global__ void sgemm64(const float* __restrict__ A, const float* __restrict__ Bm,
                        const float* __restrict__ bias, float* __restrict__ C,
                        int M, int N, int K, const float* __restrict__ res)
{
    __shared__ float As[16][64];
    __shared__ float Bs[16][64];
    int bm = blockIdx.y * 64;
    int bn = blockIdx.x * 64;
    int tid = threadIdx.x;
    int tx = tid & 15, ty = tid >> 4;
    float acc[4][4] = {};
    for (int k0 = 0; k0 < K; k0 += 16) {
        #pragma unroll
        for (int i = 0; i < 4; i++) {
            int p = tid + i*256;
            int m = p >> 4, kk = p & 15;
            As[kk][m] = A[(size_t)(bm+m)*K + k0 + kk];
        }
        #pragma unroll
        for (int i = 0; i < 4; i++) {
            int p = tid + i*256;
            int kk = p >> 6, n = p & 63;
            Bs[kk][n] = Bm[(size_t)(k0+kk)*N + bn + n];
        }
        __syncthreads();
        #pragma unroll
        for (int kk = 0; kk < 16; kk++) {
            float a[4], bb[4];
            #pragma unroll
            for (int i = 0; i < 4; i++) a[i]  = As[kk][ty*4+i];
            #pragma unroll
            for (int j = 0; j < 4; j++) bb[j] = Bs[kk][tx*4+j];
            #pragma unroll
            for (int i = 0; i < 4; i++)
                #pragma unroll
                for (int j = 0; j < 4; j++)
                    acc[i][j] += a[i]*bb[j];
        }
        __syncthreads();
    }
    #pragma unroll
    for (int i = 0; i < 4; i++) {
        int m = bm + ty*4 + i;
        #pragma unroll
        for (int j = 0; j < 4; j++) {
            int n = bn + tx*4 + j;
            float v = acc[i][j] + bias[n];
            C[(size_t)m*N + n] = v;
        }
    }
}

// ---------------- tf32 tensor-core GEMM 128x64x32, 256 thr, 8 warps -----------
// EPI: 0 = +bias; 1 = gelu(+bias); 2 = +bias + res[row]; 3 = +bias + res[remapped row] (window reverse)
template<int EPI>
__global__ void __launch_bounds__(256)
tf32gemm(const float* __restrict__ A, const float* __restrict__ Bm,
         const float* __restrict__ bias, float* __restrict__ C,
         int M, int N, int K, const float* __restrict__ res)
{
    __shared__ unsigned As[128*36];   // [m][k] stride 36 (float4-aligned, frag-read conflict-free)
    __shared__ unsigned Bs[64*36];    // [n][k] stride 36

    int tid  = threadIdx.x;
    int warp = tid >> 5, lane = tid & 31;
    int g = lane >> 2, t = lane & 3;      // groupID / threadID_in_group
    int wm = warp >> 1, wn = warp & 1;    // 4 x 2 warp grid
    int bm = blockIdx.y * 128, bn = blockIdx.x * 64;

    float acc[2][4][4];
    #pragma unroll
    for (int mi = 0; mi < 2; mi++)
        #pragma unroll
        for (int ni = 0; ni < 4; ni++)
            #pragma unroll
            for (int r = 0; r < 4; r++) acc[mi][ni][r] = 0.f;

    for (int k0 = 0; k0 < K; k0 += 32) {
        // stage A tile 128x32 (row-major source)
        #pragma unroll
        for (int i = 0; i < 4; i++) {
            int p = tid + i*256;
            int row = p >> 3, c4 = (p & 7) << 2;
            float4 v = *(const float4*)&A[(size_t)(bm+row)*K + k0 + c4];
            unsigned* dst = &As[row*36 + c4];
            dst[0] = f2tf(v.x); dst[1] = f2tf(v.y);
            dst[2] = f2tf(v.z); dst[3] = f2tf(v.w);
        }
        // stage B tile 32x64 -> transposed [n][k]
        #pragma unroll
        for (int i = 0; i < 2; i++) {
            int p = tid + i*256;
            int kk = p >> 4, n4 = (p & 15) << 2;
            float4 v = *(const float4*)&Bm[(size_t)(k0+kk)*N + bn + n4];
            Bs[(n4+0)*36 + kk] = f2tf(v.x);
            Bs[(n4+1)*36 + kk] = f2tf(v.y);
            Bs[(n4+2)*36 + kk] = f2tf(v.z);
            Bs[(n4+3)*36 + kk] = f2tf(v.w);
        }
        __syncthreads();

        #pragma unroll
        for (int ks = 0; ks < 4; ks++) {
            int kb = ks * 8;
            unsigned a[2][4], b[4][2];
            #pragma unroll
            for (int mi = 0; mi < 2; mi++) {
                int mrow = wm*32 + mi*16;
                a[mi][0] = As[(mrow +     g)*36 + kb + t    ];
                a[mi][1] = As[(mrow + 8 + g)*36 + kb + t    ];
                a[mi][2] = As[(mrow +     g)*36 + kb + t + 4];
                a[mi][3] = As[(mrow + 8 + g)*36 + kb + t + 4];
            }
            #pragma unroll
            for (int ni = 0; ni < 4; ni++) {
                int nc = wn*32 + ni*8;
                b[ni][0] = Bs[(nc + g)*36 + kb + t    ];
                b[ni][1] = Bs[(nc + g)*36 + kb + t + 4];
            }
            #pragma unroll
            for (int mi = 0; mi < 2; mi++)
                #pragma unroll
                for (int ni = 0; ni < 4; ni++) {
                    asm volatile(
                        "mma.sync.aligned.m16n8k8.row.col.f32.tf32.tf32.f32 "
                        "{%0,%1,%2,%3}, {%4,%5,%6,%7}, {%8,%9}, {%0,%1,%2,%3};"
                        : "+f"(acc[mi][ni][0]), "+f"(acc[mi][ni][1]),
                          "+f"(acc[mi][ni][2]), "+f"(acc[mi][ni][3])
                        : "r"(a[mi][0]), "r"(a[mi][1]), "r"(a[mi][2]), "r"(a[mi][3]),
                          "r"(b[ni][0]), "r"(b[ni][1]));
                }
        }
        __syncthreads();
    }

    // epilogue
    #pragma unroll
    for (int mi = 0; mi < 2; mi++) {
        #pragma unroll
        for (int half = 0; half < 2; half++) {
            int m = bm + wm*32 + mi*16 + half*8 + g;
            int outrow = m;
            if (EPI == 3) {
                int bw = m / Ntok, nt = m % Ntok;
                int bimg = bw >> 6, rem = bw & 63;
                int wh = rem >> 3, ww = rem & 7;
                int hr = wh*WS + nt/WS;
                int wc = ww*WS + nt%WS;
                outrow = bimg*(Himg*Wimg) + hr*Wimg + wc;
            }
            #pragma unroll
            for (int ni = 0; ni < 4; ni++) {
                int n = bn + wn*32 + ni*8 + t*2;
                float v0 = acc[mi][ni][half*2+0] + bias[n];
                float v1 = acc[mi][ni][half*2+1] + bias[n+1];
                if (EPI == 1) { v0 = gelu_f(v0); v1 = gelu_f(v1); }
                if (EPI == 2) { v0 += res[(size_t)m*N + n]; v1 += res[(size_t)m*N + n + 1]; }
                if (EPI == 3) { v0 += res[(size_t)outrow*N + n]; v1 += res[(size_t)outrow*N + n + 1]; }
                C[(size_t)outrow*N + n]     = v0;
                C[(size_t)outrow*N + n + 1] = v1;
            }
        }
    }
}

// ---------------- channel + spatial top-k (one block per head-window) ----------------
__global__ void topk_kernel(const float* __restrict__ wch, const float* __restrict__ bch)
{
    int bn = blockIdx.x;
    int bw = bn >> 3, hh = bn & 7;
    int tid = threadIdx.x;  // 64 threads
    __shared__ float sh[Ntok*33];
    __shared__ float feat[2*HDd];
    __shared__ float sp[HDd];
    __shared__ float tm[Ntok];
    __shared__ int   selflag[Ntok];

    for (int e = tid; e < Ntok*HDd; e += 64) {
        int n = e >> 5, d = e & 31;
        sh[n*33 + d] = g_q[((size_t)bw*Ntok + n)*Cdim + hh*HDd + d];
    }
    __syncthreads();

    if (tid < HDd) {
        float m = 0.f, mx = -1e30f;
        #pragma unroll 7
        for (int n = 0; n < Ntok; n++) {
            float v = sh[n*33 + tid];
            m += v; mx = fmaxf(mx, v);
        }
        feat[tid] = m * (1.0f/Ntok);
        feat[HDd + tid] = mx;
    }
    __syncthreads();

    if (tid < HDd) {
        float s = bch[tid];
        #pragma unroll 8
        for (int i = 0; i < 2*HDd; i++) s += feat[i]*wch[i*HDd + tid];
        sp[tid] = gelu_f(s);   // softmax is monotone per row; rank on gelu output is identical
    }
    __syncthreads();

    if (tid < HDd) {
        float v = sp[tid];
        int rank = 0;
        #pragma unroll 8
        for (int i = 0; i < HDd; i++) {
            float u = sp[i];
            rank += (u > v) || (u == v && i < tid);
        }
        bool sel = rank < KCH;
        unsigned mask = __ballot_sync(0xffffffffu, sel);
        if (sel) {
            int pos = __popc(mask & ((1u << tid) - 1));
            g_cidx[bn*KCH + pos] = tid;
        }
    }

    if (tid < Ntok) {
        float m = 0.f;
        #pragma unroll 8
        for (int d = 0; d < HDd; d++) m += sh[tid*33 + d];
        tm[tid] = m;
    }
    __syncthreads();
    if (tid < Ntok) {
        float v = tm[tid];
        int rank = 0;
        for (int i = 0; i < Ntok; i++) {
            float u = tm[i];
            rank += (u > v) || (u == v && i < tid);
        }
        selflag[tid] = (rank < KSPT) ? 1 : 0;
    }
    __syncthreads();
    if (tid < Ntok && selflag[tid]) {
        int pos = 0;
        for (int i = 0; i < tid; i++) pos += selflag[i];
        g_sidx[bn*KSPT + pos] = tid;
    }
}

// ---------------- gathers ----------------
__global__ void gather_qcha_kernel()
{
    int i = blockIdx.x * blockDim.x + threadIdx.x;
    if (i >= Mrows*(Cdim/2)) return;
    int j  = i & 15;
    int t  = i >> 4;
    int hh = t & 7;
    int rn = t >> 3;
    int n  = rn % Ntok;
    int bw = rn / Ntok;
    int c  = g_cidx[(bw*NHh + hh)*KCH + j];
    g_qc[((size_t)bw*Ntok + n)*(Cdim/2) + hh*KCH + j] =
        g_q[((size_t)bw*Ntok + n)*Cdim + hh*HDd + c];
}

__global__ void gather_vin_kernel()
{
    int i = blockIdx.x * blockDim.x + threadIdx.x;
    if (i >= BW*KSPT*Cdim) return;
    int d  = i & 31;
    int u  = i >> 5;
    int hh = u & 7;
    int w  = u >> 3;
    int t  = w % KSPT;
    int bw = w / KSPT;
    int n  = g_sidx[(bw*NHh + hh)*KSPT + t];
    g_vin[((size_t)bw*KSPT + t)*Cdim + hh*HDd + d] =
        g_q[((size_t)bw*Ntok + n)*Cdim + hh*HDd + d];
}

// ---------------- attention core (one block per window-head) ----------------
__global__ void attn_kernel(const float* __restrict__ rpb_table)
{
    int bw = blockIdx.x >> 3;
    int hh = blockIdx.x & 7;
    int bn = blockIdx.x;
    int tid = threadIdx.x;   // 128 threads

    __shared__ float s_k[Ntok][KCH];
    __shared__ float s_q[KSPT][KCH];
    __shared__ float s_v[KSPT][HDd];
    __shared__ float s_at[Ntok][KSPT];
    __shared__ int   s_si[KSPT];

    if (tid < KSPT) s_si[tid] = g_sidx[bn*KSPT + tid];
    __syncthreads();

    for (int e = tid; e < Ntok*KCH; e += 128) {
        int n = e >> 4, j = e & 15;
        s_k[n][j] = g_k[((size_t)bw*Ntok + n)*(Cdim/2) + hh*KCH + j];
    }
    for (int e = tid; e < KSPT*KCH; e += 128) {
        int t = e >> 4, j = e & 15;
        s_q[t][j] = g_qc[((size_t)bw*Ntok + s_si[t])*(Cdim/2) + hh*KCH + j] * QK_SCALE;
    }
    for (int e = tid; e < KSPT*HDd; e += 128) {
        int t = e >> 5, d = e & 31;
        s_v[t][d] = g_vp[((size_t)bw*KSPT + t)*Cdim + hh*HDd + d];
    }
    __syncthreads();

    for (int e = tid; e < Ntok*KSPT; e += 128) {
        int n = e / KSPT, t = e % KSPT;
        float s = 0.f;
        #pragma unroll
        for (int j = 0; j < KCH; j++) s += s_k[n][j]*s_q[t][j];
        int m = s_si[t];
        int di0 = n/WS - m/WS + (WS-1);
        int di1 = n%WS - m%WS + (WS-1);
        s += rpb_table[(di0*(2*WS-1) + di1)*NHh + hh];
        s_at[n][t] = s;
    }
    __syncthreads();

    if (tid < Ntok) {
        float mean = 0.f, mx = -1e30f;
        #pragma unroll
        for (int t = 0; t < KSPT; t++) {
            float v = s_at[tid][t];
            mean += v; mx = fmaxf(mx, v);
        }
        mean *= (1.0f/KSPT);
        float gate = 1.0f / (1.0f + expf(-mean));
        float sum = 0.f;
        #pragma unroll
        for (int t = 0; t < KSPT; t++) {
            float e = expf(s_at[tid][t] - mx);
            s_at[tid][t] = e; sum += e;
        }
        float sc = gate / sum;
        #pragma unroll
        for (int t = 0; t < KSPT; t++) s_at[tid][t] *= sc;
    }
    __syncthreads();

    for (int e = tid; e < Ntok*HDd; e += 128) {
        int n = e >> 5, d = e & 31;
        float s = 0.f;
        #pragma unroll
        for (int t = 0; t < KSPT; t++) s += s_at[n][t]*s_v[t][d];
        g_o[((size_t)bw*Ntok + n)*Cdim + hh*HDd + d] = s;
    }
}

// ---------------- launch ----------------
extern "C" void kernel_launch(void* const* d_in, const int* in_sizes, int n_in,
                              void* d_out, int out_size)
{
    const float* x       = (const float*)d_in[0];
    const float* norm1_g = (const float*)d_in[1];
    const float* norm1_b = (const float*)d_in[2];
    const float* wq      = (const float*)d_in[3];
    const float* bq      = (const float*)d_in[4];
    const float* wk      = (const float*)d_in[5];
    const float* bk      = (const float*)d_in[6];
    const float* wv      = (const float*)d_in[7];
    const float* bv      = (const float*)d_in[8];
    const float* wproj   = (const float*)d_in[9];
    const float* bproj   = (const float*)d_in[10];
    const float* wch     = (const float*)d_in[11];
    const float* bch     = (const float*)d_in[12];
    const float* rpb     = (const float*)d_in[13];
    const float* norm2_g = (const float*)d_in[14];
    const float* norm2_b = (const float*)d_in[15];
    const float* w1      = (const float*)d_in[16];
    const float* b1      = (const float*)d_in[17];
    const float* w2      = (const float*)d_in[18];
    const float* b2      = (const float*)d_in[19];
    float* out = (float*)d_out;

    float *xw, *q, *qc, *kk, *vin, *vp, *oo, *xr, *x2, *hb;
    cudaGetSymbolAddress((void**)&xw, g_xw);
    cudaGetSymbolAddress((void**)&q,  g_q);
    cudaGetSymbolAddress((void**)&qc, g_qc);
    cudaGetSymbolAddress((void**)&kk, g_k);
    cudaGetSymbolAddress((void**)&vin,g_vin);
    cudaGetSymbolAddress((void**)&vp, g_vp);
    cudaGetSymbolAddress((void**)&oo, g_o);
    cudaGetSymbolAddress((void**)&xr, g_xr);
    cudaGetSymbolAddress((void**)&x2, g_x2);
    cudaGetSymbolAddress((void**)&hb, g_hb);

    // 1. LN1 + window partition
    ln_kernel<0><<<Mrows, 256>>>(x, norm1_g, norm1_b, xw);

    // 2. Q = xw @ wq + bq  (EXACT fp32 — feeds top-k rankings)
    sgemm64<0><<<dim3(Cdim/64, Mrows/64), 256>>>(xw, wq, bq, q, Mrows, Cdim, Cdim, nullptr);

    // 3. channel + spatial top-k
    topk_kernel<<<BNh, 64>>>(wch, bch);

    // 4/5. gathers
    gather_qcha_kernel<<<(Mrows*(Cdim/2)+255)/256, 256>>>();
    gather_vin_kernel<<<(BW*KSPT*Cdim+255)/256, 256>>>();

    // 6. K = qcha1 @ wk + bk   (tf32 tensor cores)
    tf32gemm<0><<<dim3((Cdim/2)/64, Mrows/128), 256>>>(qc, wk, bk, kk, Mrows, Cdim/2, Cdim/2, nullptr);

    // 7. V = vin @ wv + bv
    tf32gemm<0><<<dim3(Cdim/64, (BW*KSPT)/128), 256>>>(vin, wv, bv, vp, BW*KSPT, Cdim, Cdim, nullptr);

    // 8. attention
    attn_kernel<<<BNh, 128>>>(rpb);

    // 9. out-proj + window reverse + shortcut  -> xr
    tf32gemm<3><<<dim3(Cdim/64, Mrows/128), 256>>>(oo, wproj, bproj, xr, Mrows, Cdim, Cdim, x);

    // 10. LN2
    ln_kernel<1><<<Mrows, 256>>>(xr, norm2_g, norm2_b, x2);

    // 11. h = gelu(x2 @ w1 + b1)
    tf32gemm<1><<<dim3(MLPH/64, Mrows/128), 256>>>(x2, w1, b1, hb, Mrows, MLPH, Cdim, nullptr);

    // 12. out = xr + h @ w2 + b2
    tf32gemm<2><<<dim3(Cdim/64, Mrows/128), 256>>>(hb, w2, b2, out, Mrows, Cdim, MLPH, xr);
}

// round 7
// speedup vs baseline: 2.9998x; 1.3754x over previous
#include <cuda_runtime.h>
#include <math.h>

// ---------------- problem constants ----------------
#define Bv    32
#define Himg  56
#define Wimg  56
#define Cdim  256
#define WS    7
#define NHh   8
#define HDd   32
#define KCH   16
#define KSPT  28
#define Ntok  49
#define NWb   64              // windows per image (8*8)
#define BW    (Bv*NWb)        // 2048
#define BNh   (BW*NHh)        // 16384
#define Mrows (BW*Ntok)       // 100352
#define MLPH  1024
#define QK_SCALE 0.17677669529663687f

// ---------------- scratch (device globals; no allocs allowed) ----------------
__device__ float g_xw [Mrows*Cdim];
__device__ float g_q  [Mrows*Cdim];
__device__ float g_qc [Mrows*(Cdim/2)];
__device__ float g_k  [Mrows*(Cdim/2)];
__device__ float g_vin[BW*KSPT*Cdim];
__device__ float g_vp [BW*KSPT*Cdim];
__device__ float g_o  [Mrows*Cdim];
__device__ float g_xr [Mrows*Cdim];
__device__ float g_x2 [Mrows*Cdim];
__device__ float g_hb [Mrows*MLPH];
__device__ int   g_cidx[BNh*KCH];
__device__ int   g_sidx[BNh*KSPT];

__device__ __forceinline__ float gelu_f(float v) {
    return 0.5f * v * (1.0f + erff(v * 0.7071067811865476f));
}

__device__ __forceinline__ unsigned f2tf(float f) {
    unsigned u;
    asm("cvt.rna.tf32.f32 %0, %1;" : "=r"(u) : "f"(f));
    return u;
}

__device__ __forceinline__ void mma8(float* d, const unsigned* a, const unsigned* b) {
    asm volatile("mma.sync.aligned.m16n8k8.row.col.f32.tf32.tf32.f32 "
        "{%0,%1,%2,%3}, {%4,%5,%6,%7}, {%8,%9}, {%0,%1,%2,%3};"
        : "+f"(d[0]), "+f"(d[1]), "+f"(d[2]), "+f"(d[3])
        : "r"(a[0]), "r"(a[1]), "r"(a[2]), "r"(a[3]), "r"(b[0]), "r"(b[1]));
}

// ---------------- LayerNorm (one block = one row of 256) ----------------
template<int MODE>
__global__ void ln_kernel(const float* __restrict__ x, const float* __restrict__ g,
                          const float* __restrict__ b, float* __restrict__ out)
{
    int r = blockIdx.x;
    int tid = threadIdx.x;
    float v = x[(size_t)r*Cdim + tid];
    float s = v, sq = v*v;
    __shared__ float ws[8], wq[8];
    #pragma unroll
    for (int o = 16; o > 0; o >>= 1) {
        s  += __shfl_down_sync(0xffffffffu, s,  o);
        sq += __shfl_down_sync(0xffffffffu, sq, o);
    }
    if ((tid & 31) == 0) { ws[tid >> 5] = s; wq[tid >> 5] = sq; }
    __syncthreads();
    float ts = 0.f, tq = 0.f;
    #pragma unroll
    for (int i = 0; i < 8; i++) { ts += ws[i]; tq += wq[i]; }
    float mean = ts * (1.0f/Cdim);
    float var  = tq * (1.0f/Cdim) - mean*mean;
    float rstd = rsqrtf(var + 1e-5f);
    float y = (v - mean) * rstd * g[tid] + b[tid];

    int dst;
    if (MODE == 0) {
        int bimg = r / (Himg*Wimg);
        int l    = r % (Himg*Wimg);
        int hr = l / Wimg, wc = l % Wimg;
        int wh = hr / WS, iwh = hr % WS;
        int ww = wc / WS, iww = wc % WS;
        dst = ((bimg*NWb + wh*8 + ww) * Ntok) + iwh*WS + iww;
    } else {
        dst = r;
    }
    out[(size_t)dst*Cdim + tid] = y;
}

// ---------------- tf32 tensor-core GEMM 128x128x32, cp.async double-buffered --
// 256 thr, 8 warps in 2x4 grid, each warp 64x32.
// EPI: 0 = +bias; 1 = gelu(+bias); 2 = +bias + res[row]; 3 = +bias + res[remapped row]
// PREC: 0 = plain tf32; 1 = 3xTF32 error-compensated (near-fp32 accuracy)
#define ASTRIDE 36
#define BSTRIDE 132
#define ASZ (128*ASTRIDE)
#define BSZ (32*BSTRIDE)
#define GEMM_SMEM_BYTES ((2*ASZ + 2*BSZ)*4)

template<int EPI, int PREC>
__global__ void __launch_bounds__(256)
tcgemm(const float* __restrict__ A, const float* __restrict__ Bm,
       const float* __restrict__ bias, float* __restrict__ C,
       int M, int N, int K, const float* __restrict__ res)
{
    extern __shared__ float smf[];
    float* As = smf;               // 2 buffers, [m][k] stride 36
    float* Bs = smf + 2*ASZ;       // 2 buffers, [k][n] stride 132

    int tid  = threadIdx.x;
    int warp = tid >> 5, lane = tid & 31;
    int g = lane >> 2, t = lane & 3;
    int wm = warp >> 2, wn = warp & 3;        // 2 x 4 warp grid
    int bm = blockIdx.y * 128, bn = blockIdx.x * 128;

    int arow = tid >> 3, ac4 = (tid & 7) << 2;
    int bkk  = tid >> 5, bn4 = (tid & 31) << 2;

    float acc[4][4][4];
    #pragma unroll
    for (int mi = 0; mi < 4; mi++)
        #pragma unroll
        for (int ni = 0; ni < 4; ni++)
            #pragma unroll
            for (int r = 0; r < 4; r++) acc[mi][ni][r] = 0.f;

#define STAGE(K0, BUF) do {                                                      \
        unsigned sa = (unsigned)__cvta_generic_to_shared(As + (BUF)*ASZ);        \
        unsigned sb = (unsigned)__cvta_generic_to_shared(Bs + (BUF)*BSZ);        \
        _Pragma("unroll")                                                        \
        for (int i = 0; i < 4; i++) {                                            \
            int row = arow + i*32;                                               \
            unsigned dst = sa + (unsigned)(row*ASTRIDE + ac4)*4u;                \
            const float* src = A + (size_t)(bm+row)*K + (K0) + ac4;              \
            asm volatile("cp.async.cg.shared.global [%0], [%1], 16;"             \
                         :: "r"(dst), "l"(src));                                 \
        }                                                                        \
        _Pragma("unroll")                                                        \
        for (int i = 0; i < 4; i++) {                                            \
            int kk = bkk + i*8;                                                  \
            unsigned dst = sb + (unsigned)(kk*BSTRIDE + bn4)*4u;                 \
            const float* src = Bm + (size_t)((K0)+kk)*N + bn + bn4;              \
            asm volatile("cp.async.cg.shared.global [%0], [%1], 16;"             \
                         :: "r"(dst), "l"(src));                                 \
        }                                                                        \
        asm volatile("cp.async.commit_group;");                                  \
    } while (0)

#define COMPUTE(BUF) do {                                                        \
        const float* Ab = As + (BUF)*ASZ;                                        \
        const float* Bb = Bs + (BUF)*BSZ;                                        \
        _Pragma("unroll")                                                        \
        for (int ks = 0; ks < 4; ks++) {                                         \
            int kb = ks*8;                                                       \
            unsigned ah[4][4], al[4][4];                                         \
            _Pragma("unroll")                                                    \
            for (int mi = 0; mi < 4; mi++) {                                     \
                int mrow = wm*64 + mi*16;                                        \
                float v0 = Ab[(mrow +     g)*ASTRIDE + kb + t    ];              \
                float v1 = Ab[(mrow + 8 + g)*ASTRIDE + kb + t    ];              \
                float v2 = Ab[(mrow +     g)*ASTRIDE + kb + t + 4];              \
                float v3 = Ab[(mrow + 8 + g)*ASTRIDE + kb + t + 4];              \
                ah[mi][0] = f2tf(v0); ah[mi][1] = f2tf(v1);                      \
                ah[mi][2] = f2tf(v2); ah[mi][3] = f2tf(v3);                      \
                if (PREC) {                                                      \
                    al[mi][0] = f2tf(v0 - __uint_as_float(ah[mi][0]));           \
                    al[mi][1] = f2tf(v1 - __uint_as_float(ah[mi][1]));           \
                    al[mi][2] = f2tf(v2 - __uint_as_float(ah[mi][2]));           \
                    al[mi][3] = f2tf(v3 - __uint_as_float(ah[mi][3]));           \
                }                                                                \
            }                                                                    \
            unsigned bh[4][2], bl[4][2];                                         \
            _Pragma("unroll")                                                    \
            for (int ni = 0; ni < 4; ni++) {                                     \
                int nc = wn*32 + ni*8;                                           \
                float u0 = Bb[(kb + t    )*BSTRIDE + nc + g];                    \
                float u1 = Bb[(kb + t + 4)*BSTRIDE + nc + g];                    \
                bh[ni][0] = f2tf(u0); bh[ni][1] = f2tf(u1);                      \
                if (PREC) {                                                      \
                    bl[ni][0] = f2tf(u0 - __uint_as_float(bh[ni][0]));           \
                    bl[ni][1] = f2tf(u1 - __uint_as_float(bh[ni][1]));           \
                }                                                                \
            }                                                                    \
            _Pragma("unroll")                                                    \
            for (int mi = 0; mi < 4; mi++)                                       \
                _Pragma("unroll")                                                \
                for (int ni = 0; ni < 4; ni++) {                                 \
                    if (PREC) {                                                  \
                        mma8(acc[mi][ni], al[mi], bh[ni]);                       \
                        mma8(acc[mi][ni], ah[mi], bl[ni]);                       \
                    }                                                            \
                    mma8(acc[mi][ni], ah[mi], bh[ni]);                           \
                }                                                                \
        }                                                                        \
    } while (0)

    int nch = K >> 5;
    STAGE(0, 0);
    int buf = 0;
    for (int c = 1; c < nch; c++) {
        STAGE(c*32, buf^1);
        asm volatile("cp.async.wait_group 1;");
        __syncthreads();
        COMPUTE(buf);
        __syncthreads();
        buf ^= 1;
    }
    asm volatile("cp.async.wait_group 0;");
    __syncthreads();
    COMPUTE(buf);

    // epilogue
    #pragma unroll
    for (int mi = 0; mi < 4; mi++) {
        #pragma unroll
        for (int half = 0; half < 2; half++) {
            int m = bm + wm*64 + mi*16 + half*8 + g;
            int outrow = m;
            if (EPI == 3) {
                int bw = m / Ntok, nt = m % Ntok;
                int bimg = bw >> 6, rem = bw & 63;
                int wh = rem >> 3, ww = rem & 7;
                int hr = wh*WS + nt/WS;
                int wc = ww*WS + nt%WS;
                outrow = bimg*(Himg*Wimg) + hr*Wimg + wc;
            }
            #pragma unroll
            for (int ni = 0; ni < 4; ni++) {
                int n = bn + wn*32 + ni*8 + t*2;
                float v0 = acc[mi][ni][half*2+0] + bias[n];
                float v1 = acc[mi][ni][half*2+1] + bias[n+1];
                if (EPI == 1) { v0 = gelu_f(v0); v1 = gelu_f(v1); }
                if (EPI == 2) { v0 += res[(size_t)m*N + n]; v1 += res[(size_t)m*N + n + 1]; }
                if (EPI == 3) { v0 += res[(size_t)outrow*N + n]; v1 += res[(size_t)outrow*N + n + 1]; }
                C[(size_t)outrow*N + n]     = v0;
                C[(size_t)outrow*N + n + 1] = v1;
            }
        }
    }
#undef STAGE
#undef COMPUTE
}

// ---------------- channel + spatial top-k (one block per head-window) ----------------
__global__ void topk_kernel(const float* __restrict__ wch, const float* __restrict__ bch)
{
    int bn = blockIdx.x;
    int bw = bn >> 3, hh = bn & 7;
    int tid = threadIdx.x;  // 64 threads
    __shared__ float sh[Ntok*33];
    __shared__ float feat[2*HDd];
    __shared__ float sp[HDd];
    __shared__ float tm[Ntok];
    __shared__ int   selflag[Ntok];

    for (int e = tid; e < Ntok*HDd; e += 64) {
        int n = e >> 5, d = e & 31;
        sh[n*33 + d] = g_q[((size_t)bw*Ntok + n)*Cdim + hh*HDd + d];
    }
    __syncthreads();

    if (tid < HDd) {
        float m = 0.f, mx = -1e30f;
        #pragma unroll 7
        for (int n = 0; n < Ntok; n++) {
            float v = sh[n*33 + tid];
            m += v; mx = fmaxf(mx, v);
        }
        feat[tid] = m * (1.0f/Ntok);
        feat[HDd + tid] = mx;
    }
    __syncthreads();

    if (tid < HDd) {
        float s = bch[tid];
        #pragma unroll 8
        for (int i = 0; i < 2*HDd; i++) s += feat[i]*wch[i*HDd + tid];
        sp[tid] = gelu_f(s);   // softmax is monotone per row; rank on gelu output is identical
    }
    __syncthreads();

    if (tid < HDd) {
        float v = sp[tid];
        int rank = 0;
        #pragma unroll 8
        for (int i = 0; i < HDd; i++) {
            float u = sp[i];
            rank += (u > v) || (u == v && i < tid);
        }
        bool sel = rank < KCH;
        unsigned mask = __ballot_sync(0xffffffffu, sel);
        if (sel) {
            int pos = __popc(mask & ((1u << tid) - 1));
            g_cidx[bn*KCH + pos] = tid;
        }
    }

    if (tid < Ntok) {
        float m = 0.f;
        #pragma unroll 8
        for (int d = 0; d < HDd; d++) m += sh[tid*33 + d];
        tm[tid] = m;
    }
    __syncthreads();
    if (tid < Ntok) {
        float v = tm[tid];
        int rank = 0;
        for (int i = 0; i < Ntok; i++) {
            float u = tm[i];
            rank += (u > v) || (u == v && i < tid);
        }
        selflag[tid] = (rank < KSPT) ? 1 : 0;
    }
    __syncthreads();
    if (tid < Ntok && selflag[tid]) {
        int pos = 0;
        for (int i = 0; i < tid; i++) pos += selflag[i];
        g_sidx[bn*KSPT + pos] = tid;
    }
}

// ---------------- gathers ----------------
__global__ void gather_qcha_kernel()
{
    int i = blockIdx.x * blockDim.x + threadIdx.x;
    if (i >= Mrows*(Cdim/2)) return;
    int j  = i & 15;
    int t  = i >> 4;
    int hh = t & 7;
    int rn = t >> 3;
    int n  = rn % Ntok;
    int bw = rn / Ntok;
    int c  = g_cidx[(bw*NHh + hh)*KCH + j];
    g_qc[((size_t)bw*Ntok + n)*(Cdim/2) + hh*KCH + j] =
        g_q[((size_t)bw*Ntok + n)*Cdim + hh*HDd + c];
}

__global__ void gather_vin_kernel()
{
    int i = blockIdx.x * blockDim.x + threadIdx.x;
    if (i >= BW*KSPT*Cdim) return;
    int d  = i & 31;
    int u  = i >> 5;
    int hh = u & 7;
    int w  = u >> 3;
    int t  = w % KSPT;
    int bw = w / KSPT;
    int n  = g_sidx[(bw*NHh + hh)*KSPT + t];
    g_vin[((size_t)bw*KSPT + t)*Cdim + hh*HDd + d] =
        g_q[((size_t)bw*Ntok + n)*Cdim + hh*HDd + d];
}

// ---------------- attention core (one block per window-head) ----------------
__global__ void attn_kernel(const float* __restrict__ rpb_table)
{
    int bw = blockIdx.x >> 3;
    int hh = blockIdx.x & 7;
    int bn = blockIdx.x;
    int tid = threadIdx.x;   // 128 threads

    __shared__ float s_k[Ntok][KCH];
    __shared__ float s_q[KSPT][KCH];
    __shared__ float s_v[KSPT][HDd];
    __shared__ float s_at[Ntok][KSPT];
    __shared__ int   s_si[KSPT];

    if (tid < KSPT) s_si[tid] = g_sidx[bn*KSPT + tid];
    __syncthreads();

    for (int e = tid; e < Ntok*KCH; e += 128) {
        int n = e >> 4, j = e & 15;
        s_k[n][j] = g_k[((size_t)bw*Ntok + n)*(Cdim/2) + hh*KCH + j];
    }
    for (int e = tid; e < KSPT*KCH; e += 128) {
        int t = e >> 4, j = e & 15;
        s_q[t][j] = g_qc[((size_t)bw*Ntok + s_si[t])*(Cdim/2) + hh*KCH + j] * QK_SCALE;
    }
    for (int e = tid; e < KSPT*HDd; e += 128) {
        int t = e >> 5, d = e & 31;
        s_v[t][d] = g_vp[((size_t)bw*KSPT + t)*Cdim + hh*HDd + d];
    }
    __syncthreads();

    for (int e = tid; e < Ntok*KSPT; e += 128) {
        int n = e / KSPT, t = e % KSPT;
        float s = 0.f;
        #pragma unroll
        for (int j = 0; j < KCH; j++) s += s_k[n][j]*s_q[t][j];
        int m = s_si[t];
        int di0 = n/WS - m/WS + (WS-1);
        int di1 = n%WS - m%WS + (WS-1);
        s += rpb_table[(di0*(2*WS-1) + di1)*NHh + hh];
        s_at[n][t] = s;
    }
    __syncthreads();

    if (tid < Ntok) {
        float mean = 0.f, mx = -1e30f;
        #pragma unroll
        for (int t = 0; t < KSPT; t++) {
            float v = s_at[tid][t];
            mean += v; mx = fmaxf(mx, v);
        }
        mean *= (1.0f/KSPT);
        float gate = 1.0f / (1.0f + expf(-mean));
        float sum = 0.f;
        #pragma unroll
        for (int t = 0; t < KSPT; t++) {
            float e = expf(s_at[tid][t] - mx);
            s_at[tid][t] = e; sum += e;
        }
        float sc = gate / sum;
        #pragma unroll
        for (int t = 0; t < KSPT; t++) s_at[tid][t] *= sc;
    }
    __syncthreads();

    for (int e = tid; e < Ntok*HDd; e += 128) {
        int n = e >> 5, d = e & 31;
        float s = 0.f;
        #pragma unroll
        for (int t = 0; t < KSPT; t++) s += s_at[n][t]*s_v[t][d];
        g_o[((size_t)bw*Ntok + n)*Cdim + hh*HDd + d] = s;
    }
}

// ---------------- launch ----------------
extern "C" void kernel_launch(void* const* d_in, const int* in_sizes, int n_in,
                              void* d_out, int out_size)
{
    const float* x       = (const float*)d_in[0];
    const float* norm1_g = (const float*)d_in[1];
    const float* norm1_b = (const float*)d_in[2];
    const float* wq      = (const float*)d_in[3];
    const float* bq      = (const float*)d_in[4];
    const float* wk      = (const float*)d_in[5];
    const float* bk      = (const float*)d_in[6];
    const float* wv      = (const float*)d_in[7];
    const float* bv      = (const float*)d_in[8];
    const float* wproj   = (const float*)d_in[9];
    const float* bproj   = (const float*)d_in[10];
    const float* wch     = (const float*)d_in[11];
    const float* bch     = (const float*)d_in[12];
    const float* rpb     = (const float*)d_in[13];
    const float* norm2_g = (const float*)d_in[14];
    const float* norm2_b = (const float*)d_in[15];
    const float* w1      = (const float*)d_in[16];
    const float* b1      = (const float*)d_in[17];
    const float* w2      = (const float*)d_in[18];
    const float* b2      = (const float*)d_in[19];
    float* out = (float*)d_out;

    float *xw, *q, *qc, *kk, *vin, *vp, *oo, *xr, *x2, *hb;
    cudaGetSymbolAddress((void**)&xw, g_xw);
    cudaGetSymbolAddress((void**)&q,  g_q);
    cudaGetSymbolAddress((void**)&qc, g_qc);
    cudaGetSymbolAddress((void**)&kk, g_k);
    cudaGetSymbolAddress((void**)&vin,g_vin);
    cudaGetSymbolAddress((void**)&vp, g_vp);
    cudaGetSymbolAddress((void**)&oo, g_o);
    cudaGetSymbolAddress((void**)&xr, g_xr);
    cudaGetSymbolAddress((void**)&x2, g_x2);
    cudaGetSymbolAddress((void**)&hb, g_hb);

    static bool attr_done = false;
    if (!attr_done) {
        cudaFuncSetAttribute(tcgemm<0,0>, cudaFuncAttributeMaxDynamicSharedMemorySize, GEMM_SMEM_BYTES);
        cudaFuncSetAttribute(tcgemm<1,0>, cudaFuncAttributeMaxDynamicSharedMemorySize, GEMM_SMEM_BYTES);
        cudaFuncSetAttribute(tcgemm<2,0>, cudaFuncAttributeMaxDynamicSharedMemorySize, GEMM_SMEM_BYTES);
        cudaFuncSetAttribute(tcgemm<3,0>, cudaFuncAttributeMaxDynamicSharedMemorySize, GEMM_SMEM_BYTES);
        cudaFuncSetAttribute(tcgemm<0,1>, cudaFuncAttributeMaxDynamicSharedMemorySize, GEMM_SMEM_BYTES);
        attr_done = true;
    }

    // 1. LN1 + window partition
    ln_kernel<0><<<Mrows, 256>>>(x, norm1_g, norm1_b, xw);

    // 2. Q = xw @ wq + bq  (3xTF32 — near-fp32 accuracy, feeds top-k rankings)
    tcgemm<0,1><<<dim3(Cdim/128, Mrows/128), 256, GEMM_SMEM_BYTES>>>(xw, wq, bq, q, Mrows, Cdim, Cdim, nullptr);

    // 3. channel + spatial top-k
    topk_kernel<<<BNh, 64>>>(wch, bch);

    // 4/5. gathers
    gather_qcha_kernel<<<(Mrows*(Cdim/2)+255)/256, 256>>>();
    gather_vin_kernel<<<(BW*KSPT*Cdim+255)/256, 256>>>();

    // 6. K = qcha1 @ wk + bk
    tcgemm<0,0><<<dim3((Cdim/2)/128, Mrows/128), 256, GEMM_SMEM_BYTES>>>(qc, wk, bk, kk, Mrows, Cdim/2, Cdim/2, nullptr);

    // 7. V = vin @ wv + bv
    tcgemm<0,0><<<dim3(Cdim/128, (BW*KSPT)/128), 256, GEMM_SMEM_BYTES>>>(vin, wv, bv, vp, BW*KSPT, Cdim, Cdim, nullptr);

    // 8. attention
    attn_kernel<<<BNh, 128>>>(rpb);

    // 9. out-proj + window reverse + shortcut  -> xr
    tcgemm<3,0><<<dim3(Cdim/128, Mrows/128), 256, GEMM_SMEM_BYTES>>>(oo, wproj, bproj, xr, Mrows, Cdim, Cdim, x);

    // 10. LN2
    ln_kernel<1><<<Mrows, 256>>>(xr, norm2_g, norm2_b, x2);

    // 11. h = gelu(x2 @ w1 + b1)
    tcgemm<1,0><<<dim3(MLPH/128, Mrows/128), 256, GEMM_SMEM_BYTES>>>(x2, w1, b1, hb, Mrows, MLPH, Cdim, nullptr);

    // 12. out = xr + h @ w2 + b2
    tcgemm<2,0><<<dim3(Cdim/128, Mrows/128), 256, GEMM_SMEM_BYTES>>>(hb, w2, b2, out, Mrows, Cdim, MLPH, xr);
}

// round 8
// speedup vs baseline: 3.8588x; 1.2863x over previous
#include <cuda_runtime.h>
#include <cuda_bf16.h>
#include <math.h>

// ---------------- problem constants ----------------
#define Bv    32
#define Himg  56
#define Wimg  56
#define Cdim  256
#define WS    7
#define NHh   8
#define HDd   32
#define KCH   16
#define KSPT  28
#define Ntok  49
#define NWb   64              // windows per image (8*8)
#define BW    (Bv*NWb)        // 2048
#define BNh   (BW*NHh)        // 16384
#define Mrows (BW*Ntok)       // 100352
#define MLPH  1024
#define QK_SCALE 0.17677669529663687f

// ---------------- scratch (device globals; no allocs allowed) ----------------
__device__ float          g_xw [Mrows*Cdim];          // fp32: feeds exact Q GEMM
__device__ float          g_q  [Mrows*Cdim];          // fp32: feeds top-k
__device__ __nv_bfloat16  g_qc [Mrows*(Cdim/2)];
__device__ float          g_k  [Mrows*(Cdim/2)];
__device__ __nv_bfloat16  g_vin[BW*KSPT*Cdim];
__device__ float          g_vp [BW*KSPT*Cdim];
__device__ __nv_bfloat16  g_o  [Mrows*Cdim];
__device__ float          g_xr [Mrows*Cdim];          // fp32 residual
__device__ __nv_bfloat16  g_x2 [Mrows*Cdim];
__device__ __nv_bfloat16  g_hb [Mrows*MLPH];
__device__ int   g_cidx[BNh*KCH];
__device__ int   g_sidx[BNh*KSPT];
// transposed bf16 weights [N][K]
__device__ __nv_bfloat16  g_wkb[(Cdim/2)*(Cdim/2)];
__device__ __nv_bfloat16  g_wvb[Cdim*Cdim];
__device__ __nv_bfloat16  g_wpb[Cdim*Cdim];
__device__ __nv_bfloat16  g_w1b[Cdim*MLPH];
__device__ __nv_bfloat16  g_w2b[MLPH*Cdim];

__device__ __forceinline__ float gelu_f(float v) {
    return 0.5f * v * (1.0f + erff(v * 0.7071067811865476f));
}

__device__ __forceinline__ unsigned f2tf(float f) {
    unsigned u;
    asm("cvt.rna.tf32.f32 %0, %1;" : "=r"(u) : "f"(f));
    return u;
}

__device__ __forceinline__ void mma8(float* d, const unsigned* a, const unsigned* b) {
    asm volatile("mma.sync.aligned.m16n8k8.row.col.f32.tf32.tf32.f32 "
        "{%0,%1,%2,%3}, {%4,%5,%6,%7}, {%8,%9}, {%0,%1,%2,%3};"
        : "+f"(d[0]), "+f"(d[1]), "+f"(d[2]), "+f"(d[3])
        : "r"(a[0]), "r"(a[1]), "r"(a[2]), "r"(a[3]), "r"(b[0]), "r"(b[1]));
}

__device__ __forceinline__ void mma16(float* d, const unsigned* a, const unsigned* b) {
    asm volatile("mma.sync.aligned.m16n8k16.row.col.f32.bf16.bf16.f32 "
        "{%0,%1,%2,%3}, {%4,%5,%6,%7}, {%8,%9}, {%0,%1,%2,%3};"
        : "+f"(d[0]), "+f"(d[1]), "+f"(d[2]), "+f"(d[3])
        : "r"(a[0]), "r"(a[1]), "r"(a[2]), "r"(a[3]), "r"(b[0]), "r"(b[1]));
}

// ---------------- weight transpose + bf16 convert: in [K][N] -> out [N][K] ----
__global__ void convw_kernel(const float* __restrict__ in, __nv_bfloat16* __restrict__ out,
                             int K, int N)
{
    int i = blockIdx.x * 256 + threadIdx.x;
    if (i >= K*N) return;
    int k = i / N, n = i % N;
    out[n*K + k] = __float2bfloat16(in[i]);
}

// ---------------- LayerNorm (one block = one row of 256) ----------------
// MODE 0: window-partition remap, fp32 out. MODE 1: identity, bf16 out.
template<int MODE>
__global__ void ln_kernel(const float* __restrict__ x, const float* __restrict__ g,
                          const float* __restrict__ b, void* __restrict__ outp)
{
    int r = blockIdx.x;
    int tid = threadIdx.x;
    float v = x[(size_t)r*Cdim + tid];
    float s = v, sq = v*v;
    __shared__ float ws[8], wq[8];
    #pragma unroll
    for (int o = 16; o > 0; o >>= 1) {
        s  += __shfl_down_sync(0xffffffffu, s,  o);
        sq += __shfl_down_sync(0xffffffffu, sq, o);
    }
    if ((tid & 31) == 0) { ws[tid >> 5] = s; wq[tid >> 5] = sq; }
    __syncthreads();
    float ts = 0.f, tq = 0.f;
    #pragma unroll
    for (int i = 0; i < 8; i++) { ts += ws[i]; tq += wq[i]; }
    float mean = ts * (1.0f/Cdim);
    float var  = tq * (1.0f/Cdim) - mean*mean;
    float rstd = rsqrtf(var + 1e-5f);
    float y = (v - mean) * rstd * g[tid] + b[tid];

    if (MODE == 0) {
        int bimg = r / (Himg*Wimg);
        int l    = r % (Himg*Wimg);
        int hr = l / Wimg, wc = l % Wimg;
        int wh = hr / WS, iwh = hr % WS;
        int ww = wc / WS, iww = wc % WS;
        int dst = ((bimg*NWb + wh*8 + ww) * Ntok) + iwh*WS + iww;
        ((float*)outp)[(size_t)dst*Cdim + tid] = y;
    } else {
        ((__nv_bfloat16*)outp)[(size_t)r*Cdim + tid] = __float2bfloat16(y);
    }
}

// ---------------- tf32 tensor-core GEMM (Q only: 3xTF32 compensated) ---------
#define ASTRIDE 36
#define BSTRIDE 132
#define ASZ (128*ASTRIDE)
#define BSZ (32*BSTRIDE)
#define GEMM_SMEM_BYTES ((2*ASZ + 2*BSZ)*4)

__global__ void __launch_bounds__(256)
tcgemm_q(const float* __restrict__ A, const float* __restrict__ Bm,
         const float* __restrict__ bias, float* __restrict__ C,
         int M, int N, int K)
{
    extern __shared__ float smf[];
    float* As = smf;
    float* Bs = smf + 2*ASZ;

    int tid  = threadIdx.x;
    int warp = tid >> 5, lane = tid & 31;
    int g = lane >> 2, t = lane & 3;
    int wm = warp >> 2, wn = warp & 3;
    int bm = blockIdx.y * 128, bn = blockIdx.x * 128;

    int arow = tid >> 3, ac4 = (tid & 7) << 2;
    int bkk  = tid >> 5, bn4 = (tid & 31) << 2;

    float acc[4][4][4];
    #pragma unroll
    for (int mi = 0; mi < 4; mi++)
        #pragma unroll
        for (int ni = 0; ni < 4; ni++)
            #pragma unroll
            for (int r = 0; r < 4; r++) acc[mi][ni][r] = 0.f;

#define QSTAGE(K0, BUF) do {                                                     \
        unsigned sa = (unsigned)__cvta_generic_to_shared(As + (BUF)*ASZ);        \
        unsigned sb = (unsigned)__cvta_generic_to_shared(Bs + (BUF)*BSZ);        \
        _Pragma("unroll")                                                        \
        for (int i = 0; i < 4; i++) {                                            \
            int row = arow + i*32;                                               \
            unsigned dst = sa + (unsigned)(row*ASTRIDE + ac4)*4u;                \
            const float* src = A + (size_t)(bm+row)*K + (K0) + ac4;              \
            asm volatile("cp.async.cg.shared.global [%0], [%1], 16;"             \
                         :: "r"(dst), "l"(src));                                 \
        }                                                                        \
        _Pragma("unroll")                                                        \
        for (int i = 0; i < 4; i++) {                                            \
            int kk = bkk + i*8;                                                  \
            unsigned dst = sb + (unsigned)(kk*BSTRIDE + bn4)*4u;                 \
            const float* src = Bm + (size_t)((K0)+kk)*N + bn + bn4;              \
            asm volatile("cp.async.cg.shared.global [%0], [%1], 16;"             \
                         :: "r"(dst), "l"(src));                                 \
        }                                                                        \
        asm volatile("cp.async.commit_group;");                                  \
    } while (0)

#define QCOMPUTE(BUF) do {                                                       \
        const float* Ab = As + (BUF)*ASZ;                                        \
        const float* Bb = Bs + (BUF)*BSZ;                                        \
        _Pragma("unroll")                                                        \
        for (int ks = 0; ks < 4; ks++) {                                         \
            int kb = ks*8;                                                       \
            unsigned ah[4][4], al[4][4];                                         \
            _Pragma("unroll")                                                    \
            for (int mi = 0; mi < 4; mi++) {                                     \
                int mrow = wm*64 + mi*16;                                        \
                float v0 = Ab[(mrow +     g)*ASTRIDE + kb + t    ];              \
                float v1 = Ab[(mrow + 8 + g)*ASTRIDE + kb + t    ];              \
                float v2 = Ab[(mrow +     g)*ASTRIDE + kb + t + 4];              \
                float v3 = Ab[(mrow + 8 + g)*ASTRIDE + kb + t + 4];              \
                ah[mi][0] = f2tf(v0); ah[mi][1] = f2tf(v1);                      \
                ah[mi][2] = f2tf(v2); ah[mi][3] = f2tf(v3);                      \
                al[mi][0] = f2tf(v0 - __uint_as_float(ah[mi][0]));               \
                al[mi][1] = f2tf(v1 - __uint_as_float(ah[mi][1]));               \
                al[mi][2] = f2tf(v2 - __uint_as_float(ah[mi][2]));               \
                al[mi][3] = f2tf(v3 - __uint_as_float(ah[mi][3]));               \
            }                                                                    \
            unsigned bh[4][2], bl[4][2];                                         \
            _Pragma("unroll")                                                    \
            for (int ni = 0; ni < 4; ni++) {                                     \
                int nc = wn*32 + ni*8;                                           \
                float u0 = Bb[(kb + t    )*BSTRIDE + nc + g];                    \
                float u1 = Bb[(kb + t + 4)*BSTRIDE + nc + g];                    \
                bh[ni][0] = f2tf(u0); bh[ni][1] = f2tf(u1);                      \
                bl[ni][0] = f2tf(u0 - __uint_as_float(bh[ni][0]));               \
                bl[ni][1] = f2tf(u1 - __uint_as_float(bh[ni][1]));               \
            }                                                                    \
            _Pragma("unroll")                                                    \
            for (int mi = 0; mi < 4; mi++)                                       \
                _Pragma("unroll")                                                \
                for (int ni = 0; ni < 4; ni++) {                                 \
                    mma8(acc[mi][ni], al[mi], bh[ni]);                           \
                    mma8(acc[mi][ni], ah[mi], bl[ni]);                           \
                    mma8(acc[mi][ni], ah[mi], bh[ni]);                           \
                }                                                                \
        }                                                                        \
    } while (0)

    int nch = K >> 5;
    QSTAGE(0, 0);
    int buf = 0;
    for (int c = 1; c < nch; c++) {
        QSTAGE(c*32, buf^1);
        asm volatile("cp.async.wait_group 1;");
        __syncthreads();
        QCOMPUTE(buf);
        __syncthreads();
        buf ^= 1;
    }
    asm volatile("cp.async.wait_group 0;");
    __syncthreads();
    QCOMPUTE(buf);

    #pragma unroll
    for (int mi = 0; mi < 4; mi++) {
        #pragma unroll
        for (int half = 0; half < 2; half++) {
            int m = bm + wm*64 + mi*16 + half*8 + g;
            #pragma unroll
            for (int ni = 0; ni < 4; ni++) {
                int n = bn + wn*32 + ni*8 + t*2;
                C[(size_t)m*N + n]     = acc[mi][ni][half*2+0] + bias[n];
                C[(size_t)m*N + n + 1] = acc[mi][ni][half*2+1] + bias[n+1];
            }
        }
    }
#undef QSTAGE
#undef QCOMPUTE
}

// ---------------- bf16 tensor-core GEMM 128x128x32, cp.async double-buffered --
// A: [M][K] bf16 row-major. Bt: [N][K] bf16 (pre-transposed). 8 warps 2x4, warp 64x32.
// EPI: 0=+bias; 1=gelu(+bias); 2=+bias+res[m]; 3=+bias+res[remap] (window reverse)
// OUTBF: 1 -> store bf16, else fp32
#define BH  40            // halves per smem row
#define BHW 20            // words per smem row
#define TILEH (128*BH)

template<int EPI, int OUTBF>
__global__ void __launch_bounds__(256)
bfgemm(const __nv_bfloat16* __restrict__ A, const __nv_bfloat16* __restrict__ Bt,
       const float* __restrict__ bias, void* __restrict__ Cout,
       int M, int N, int K, const float* __restrict__ res)
{
    __shared__ __nv_bfloat16 sA[2*TILEH];
    __shared__ __nv_bfloat16 sB[2*TILEH];

    int tid  = threadIdx.x;
    int warp = tid >> 5, lane = tid & 31;
    int g = lane >> 2, t = lane & 3;
    int wm = warp >> 2, wn = warp & 3;
    int bm = blockIdx.y * 128, bn = blockIdx.x * 128;

    float acc[4][4][4];
    #pragma unroll
    for (int mi = 0; mi < 4; mi++)
        #pragma unroll
        for (int ni = 0; ni < 4; ni++)
            #pragma unroll
            for (int r = 0; r < 4; r++) acc[mi][ni][r] = 0.f;

#define BSTAGE(K0, BUF) do {                                                     \
        unsigned sa = (unsigned)__cvta_generic_to_shared(sA + (BUF)*TILEH);      \
        unsigned sb = (unsigned)__cvta_generic_to_shared(sB + (BUF)*TILEH);      \
        _Pragma("unroll")                                                        \
        for (int i = 0; i < 2; i++) {                                            \
            int p = tid + i*256;                                                 \
            int row = p >> 2, c8 = (p & 3) << 3;                                 \
            unsigned dsta = sa + (unsigned)(row*BH + c8)*2u;                     \
            const __nv_bfloat16* srca = A + (size_t)(bm+row)*K + (K0) + c8;      \
            asm volatile("cp.async.cg.shared.global [%0], [%1], 16;"             \
                         :: "r"(dsta), "l"(srca));                               \
            unsigned dstb = sb + (unsigned)(row*BH + c8)*2u;                     \
            const __nv_bfloat16* srcb = Bt + (size_t)(bn+row)*K + (K0) + c8;     \
            asm volatile("cp.async.cg.shared.global [%0], [%1], 16;"             \
                         :: "r"(dstb), "l"(srcb));                               \
        }                                                                        \
        asm volatile("cp.async.commit_group;");                                  \
    } while (0)

#define BCOMPUTE(BUF) do {                                                       \
        const unsigned* Ab = (const unsigned*)(sA + (BUF)*TILEH);                \
        const unsigned* Bb = (const unsigned*)(sB + (BUF)*TILEH);                \
        _Pragma("unroll")                                                        \
        for (int ks = 0; ks < 2; ks++) {                                         \
            int kw = ks*8;                                                       \
            unsigned a[4][4], b[4][2];                                           \
            _Pragma("unroll")                                                    \
            for (int mi = 0; mi < 4; mi++) {                                     \
                int mrow = wm*64 + mi*16;                                        \
                a[mi][0] = Ab[(mrow +     g)*BHW + kw + t    ];                  \
                a[mi][1] = Ab[(mrow + 8 + g)*BHW + kw + t    ];                  \
                a[mi][2] = Ab[(mrow +     g)*BHW + kw + t + 4];                  \
                a[mi][3] = Ab[(mrow + 8 + g)*BHW + kw + t + 4];                  \
            }                                                                    \
            _Pragma("unroll")                                                    \
            for (int ni = 0; ni < 4; ni++) {                                     \
                int nc = wn*32 + ni*8;                                           \
                b[ni][0] = Bb[(nc + g)*BHW + kw + t    ];                        \
                b[ni][1] = Bb[(nc + g)*BHW + kw + t + 4];                        \
            }                                                                    \
            _Pragma("unroll")                                                    \
            for (int mi = 0; mi < 4; mi++)                                       \
                _Pragma("unroll")                                                \
                for (int ni = 0; ni < 4; ni++)                                   \
                    mma16(acc[mi][ni], a[mi], b[ni]);                            \
        }                                                                        \
    } while (0)

    int nch = K >> 5;
    BSTAGE(0, 0);
    int buf = 0;
    for (int c = 1; c < nch; c++) {
        BSTAGE(c*32, buf^1);
        asm volatile("cp.async.wait_group 1;");
        __syncthreads();
        BCOMPUTE(buf);
        __syncthreads();
        buf ^= 1;
    }
    asm volatile("cp.async.wait_group 0;");
    __syncthreads();
    BCOMPUTE(buf);

    // epilogue
    #pragma unroll
    for (int mi = 0; mi < 4; mi++) {
        #pragma unroll
        for (int half = 0; half < 2; half++) {
            int m = bm + wm*64 + mi*16 + half*8 + g;
            int outrow = m;
            if (EPI == 3) {
                int bw = m / Ntok, nt = m % Ntok;
                int bimg = bw >> 6, rem = bw & 63;
                int wh = rem >> 3, ww = rem & 7;
                int hr = wh*WS + nt/WS;
                int wc = ww*WS + nt%WS;
                outrow = bimg*(Himg*Wimg) + hr*Wimg + wc;
            }
            #pragma unroll
            for (int ni = 0; ni < 4; ni++) {
                int n = bn + wn*32 + ni*8 + t*2;
                float v0 = acc[mi][ni][half*2+0] + bias[n];
                float v1 = acc[mi][ni][half*2+1] + bias[n+1];
                if (EPI == 1) { v0 = gelu_f(v0); v1 = gelu_f(v1); }
                if (EPI == 2) { v0 += res[(size_t)m*N + n]; v1 += res[(size_t)m*N + n + 1]; }
                if (EPI == 3) { v0 += res[(size_t)outrow*N + n]; v1 += res[(size_t)outrow*N + n + 1]; }
                if (OUTBF) {
                    __nv_bfloat162 p; p.x = __float2bfloat16(v0); p.y = __float2bfloat16(v1);
                    *(__nv_bfloat162*)((__nv_bfloat16*)Cout + (size_t)outrow*N + n) = p;
                } else {
                    float* Cf = (float*)Cout;
                    Cf[(size_t)outrow*N + n]     = v0;
                    Cf[(size_t)outrow*N + n + 1] = v1;
                }
            }
        }
    }
#undef BSTAGE
#undef BCOMPUTE
}

// ---------------- channel + spatial top-k (one block per head-window) ----------------
__global__ void topk_kernel(const float* __restrict__ wch, const float* __restrict__ bch)
{
    int bn = blockIdx.x;
    int bw = bn >> 3, hh = bn & 7;
    int tid = threadIdx.x;  // 64 threads
    __shared__ float sh[Ntok*33];
    __shared__ float feat[2*HDd];
    __shared__ float sp[HDd];
    __shared__ float tm[Ntok];
    __shared__ int   selflag[Ntok];

    for (int e = tid; e < Ntok*HDd; e += 64) {
        int n = e >> 5, d = e & 31;
        sh[n*33 + d] = g_q[((size_t)bw*Ntok + n)*Cdim + hh*HDd + d];
    }
    __syncthreads();

    if (tid < HDd) {
        float m = 0.f, mx = -1e30f;
        #pragma unroll 7
        for (int n = 0; n < Ntok; n++) {
            float v = sh[n*33 + tid];
            m += v; mx = fmaxf(mx, v);
        }
        feat[tid] = m * (1.0f/Ntok);
        feat[HDd + tid] = mx;
    }
    __syncthreads();

    if (tid < HDd) {
        float s = bch[tid];
        #pragma unroll 8
        for (int i = 0; i < 2*HDd; i++) s += feat[i]*wch[i*HDd + tid];
        sp[tid] = gelu_f(s);
    }
    __syncthreads();

    if (tid < HDd) {
        float v = sp[tid];
        int rank = 0;
        #pragma unroll 8
        for (int i = 0; i < HDd; i++) {
            float u = sp[i];
            rank += (u > v) || (u == v && i < tid);
        }
        bool sel = rank < KCH;
        unsigned mask = __ballot_sync(0xffffffffu, sel);
        if (sel) {
            int pos = __popc(mask & ((1u << tid) - 1));
            g_cidx[bn*KCH + pos] = tid;
        }
    }

    if (tid < Ntok) {
        float m = 0.f;
        #pragma unroll 8
        for (int d = 0; d < HDd; d++) m += sh[tid*33 + d];
        tm[tid] = m;
    }
    __syncthreads();
    if (tid < Ntok) {
        float v = tm[tid];
        int rank = 0;
        for (int i = 0; i < Ntok; i++) {
            float u = tm[i];
            rank += (u > v) || (u == v && i < tid);
        }
        selflag[tid] = (rank < KSPT) ? 1 : 0;
    }
    __syncthreads();
    if (tid < Ntok && selflag[tid]) {
        int pos = 0;
        for (int i = 0; i < tid; i++) pos += selflag[i];
        g_sidx[bn*KSPT + pos] = tid;
    }
}

// ---------------- gathers (fp32 g_q -> bf16 GEMM inputs) ----------------
__global__ void gather_qcha_kernel()
{
    int i = blockIdx.x * blockDim.x + threadIdx.x;
    if (i >= Mrows*(Cdim/2)) return;
    int j  = i & 15;
    int t  = i >> 4;
    int hh = t & 7;
    int rn = t >> 3;
    int n  = rn % Ntok;
    int bw = rn / Ntok;
    int c  = g_cidx[(bw*NHh + hh)*KCH + j];
    g_qc[((size_t)bw*Ntok + n)*(Cdim/2) + hh*KCH + j] =
        __float2bfloat16(g_q[((size_t)bw*Ntok + n)*Cdim + hh*HDd + c]);
}

__global__ void gather_vin_kernel()
{
    int i = blockIdx.x * blockDim.x + threadIdx.x;
    if (i >= BW*KSPT*Cdim) return;
    int d  = i & 31;
    int u  = i >> 5;
    int hh = u & 7;
    int w  = u >> 3;
    int t  = w % KSPT;
    int bw = w / KSPT;
    int n  = g_sidx[(bw*NHh + hh)*KSPT + t];
    g_vin[((size_t)bw*KSPT + t)*Cdim + hh*HDd + d] =
        __float2bfloat16(g_q[((size_t)bw*Ntok + n)*Cdim + hh*HDd + d]);
}

// ---------------- attention core (one block per window-head) ----------------
__global__ void attn_kernel(const float* __restrict__ rpb_table)
{
    int bw = blockIdx.x >> 3;
    int hh = blockIdx.x & 7;
    int bn = blockIdx.x;
    int tid = threadIdx.x;   // 128 threads

    __shared__ float s_k[Ntok][KCH];
    __shared__ float s_q[KSPT][KCH];
    __shared__ float s_v[KSPT][HDd];
    __shared__ float s_at[Ntok][KSPT];
    __shared__ int   s_si[KSPT];

    if (tid < KSPT) s_si[tid] = g_sidx[bn*KSPT + tid];
    __syncthreads();

    for (int e = tid; e < Ntok*KCH; e += 128) {
        int n = e >> 4, j = e & 15;
        s_k[n][j] = g_k[((size_t)bw*Ntok + n)*(Cdim/2) + hh*KCH + j];
    }
    for (int e = tid; e < KSPT*KCH; e += 128) {
        int t = e >> 4, j = e & 15;
        s_q[t][j] = __bfloat162float(g_qc[((size_t)bw*Ntok + s_si[t])*(Cdim/2) + hh*KCH + j]) * QK_SCALE;
    }
    for (int e = tid; e < KSPT*HDd; e += 128) {
        int t = e >> 5, d = e & 31;
        s_v[t][d] = g_vp[((size_t)bw*KSPT + t)*Cdim + hh*HDd + d];
    }
    __syncthreads();

    for (int e = tid; e < Ntok*KSPT; e += 128) {
        int n = e / KSPT, t = e % KSPT;
        float s = 0.f;
        #pragma unroll
        for (int j = 0; j < KCH; j++) s += s_k[n][j]*s_q[t][j];
        int m = s_si[t];
        int di0 = n/WS - m/WS + (WS-1);
        int di1 = n%WS - m%WS + (WS-1);
        s += rpb_table[(di0*(2*WS-1) + di1)*NHh + hh];
        s_at[n][t] = s;
    }
    __syncthreads();

    if (tid < Ntok) {
        float mean = 0.f, mx = -1e30f;
        #pragma unroll
        for (int t = 0; t < KSPT; t++) {
            float v = s_at[tid][t];
            mean += v; mx = fmaxf(mx, v);
        }
        mean *= (1.0f/KSPT);
        float gate = 1.0f / (1.0f + expf(-mean));
        float sum = 0.f;
        #pragma unroll
        for (int t = 0; t < KSPT; t++) {
            float e = expf(s_at[tid][t] - mx);
            s_at[tid][t] = e; sum += e;
        }
        float sc = gate / sum;
        #pragma unroll
        for (int t = 0; t < KSPT; t++) s_at[tid][t] *= sc;
    }
    __syncthreads();

    for (int e = tid; e < Ntok*HDd; e += 128) {
        int n = e >> 5, d = e & 31;
        float s = 0.f;
        #pragma unroll
        for (int t = 0; t < KSPT; t++) s += s_at[n][t]*s_v[t][d];
        g_o[((size_t)bw*Ntok + n)*Cdim + hh*HDd + d] = __float2bfloat16(s);
    }
}

// ---------------- launch ----------------
extern "C" void kernel_launch(void* const* d_in, const int* in_sizes, int n_in,
                              void* d_out, int out_size)
{
    const float* x       = (const float*)d_in[0];
    const float* norm1_g = (const float*)d_in[1];
    const float* norm1_b = (const float*)d_in[2];
    const float* wq      = (const float*)d_in[3];
    const float* bq      = (const float*)d_in[4];
    const float* wk      = (const float*)d_in[5];
    const float* bk      = (const float*)d_in[6];
    const float* wv      = (const float*)d_in[7];
    const float* bv      = (const float*)d_in[8];
    const float* wproj   = (const float*)d_in[9];
    const float* bproj   = (const float*)d_in[10];
    const float* wch     = (const float*)d_in[11];
    const float* bch     = (const float*)d_in[12];
    const float* rpb     = (const float*)d_in[13];
    const float* norm2_g = (const float*)d_in[14];
    const float* norm2_b = (const float*)d_in[15];
    const float* w1      = (const float*)d_in[16];
    const float* b1      = (const float*)d_in[17];
    const float* w2      = (const float*)d_in[18];
    const float* b2      = (const float*)d_in[19];
    float* out = (float*)d_out;

    float *xw, *q, *kk, *vp, *xr;
    __nv_bfloat16 *qc, *vin, *oo, *x2, *hb, *wkb, *wvb, *wpb, *w1b, *w2b;
    cudaGetSymbolAddress((void**)&xw, g_xw);
    cudaGetSymbolAddress((void**)&q,  g_q);
    cudaGetSymbolAddress((void**)&qc, g_qc);
    cudaGetSymbolAddress((void**)&kk, g_k);
    cudaGetSymbolAddress((void**)&vin,g_vin);
    cudaGetSymbolAddress((void**)&vp, g_vp);
    cudaGetSymbolAddress((void**)&oo, g_o);
    cudaGetSymbolAddress((void**)&xr, g_xr);
    cudaGetSymbolAddress((void**)&x2, g_x2);
    cudaGetSymbolAddress((void**)&hb, g_hb);
    cudaGetSymbolAddress((void**)&wkb, g_wkb);
    cudaGetSymbolAddress((void**)&wvb, g_wvb);
    cudaGetSymbolAddress((void**)&wpb, g_wpb);
    cudaGetSymbolAddress((void**)&w1b, g_w1b);
    cudaGetSymbolAddress((void**)&w2b, g_w2b);

    static bool attr_done = false;
    if (!attr_done) {
        cudaFuncSetAttribute(tcgemm_q, cudaFuncAttributeMaxDynamicSharedMemorySize, GEMM_SMEM_BYTES);
        attr_done = true;
    }

    // 0. weight transposes -> bf16 [N][K]
    convw_kernel<<<((Cdim/2)*(Cdim/2)+255)/256, 256>>>(wk, wkb, Cdim/2, Cdim/2);
    convw_kernel<<<(Cdim*Cdim+255)/256, 256>>>(wv, wvb, Cdim, Cdim);
    convw_kernel<<<(Cdim*Cdim+255)/256, 256>>>(wproj, wpb, Cdim, Cdim);
    convw_kernel<<<(Cdim*MLPH+255)/256, 256>>>(w1, w1b, Cdim, MLPH);
    convw_kernel<<<(MLPH*Cdim+255)/256, 256>>>(w2, w2b, MLPH, Cdim);

    // 1. LN1 + window partition (fp32 out for Q)
    ln_kernel<0><<<Mrows, 256>>>(x, norm1_g, norm1_b, xw);

    // 2. Q = xw @ wq + bq  (3xTF32 — near-fp32, feeds top-k rankings)
    tcgemm_q<<<dim3(Cdim/128, Mrows/128), 256, GEMM_SMEM_BYTES>>>(xw, wq, bq, q, Mrows, Cdim, Cdim);

    // 3. channel + spatial top-k
    topk_kernel<<<BNh, 64>>>(wch, bch);

    // 4/5. gathers (bf16 out)
    gather_qcha_kernel<<<(Mrows*(Cdim/2)+255)/256, 256>>>();
    gather_vin_kernel<<<(BW*KSPT*Cdim+255)/256, 256>>>();

    // 6. K = qcha1 @ wk + bk   (bf16 TC)
    bfgemm<0,0><<<dim3((Cdim/2)/128, Mrows/128), 256>>>(qc, wkb, bk, kk, Mrows, Cdim/2, Cdim/2, nullptr);

    // 7. V = vin @ wv + bv
    bfgemm<0,0><<<dim3(Cdim/128, (BW*KSPT)/128), 256>>>(vin, wvb, bv, vp, BW*KSPT, Cdim, Cdim, nullptr);

    // 8. attention (bf16 out)
    attn_kernel<<<BNh, 128>>>(rpb);

    // 9. out-proj + window reverse + shortcut  -> xr (fp32)
    bfgemm<3,0><<<dim3(Cdim/128, Mrows/128), 256>>>(oo, wpb, bproj, xr, Mrows, Cdim, Cdim, x);

    // 10. LN2 (bf16 out)
    ln_kernel<1><<<Mrows, 256>>>(xr, norm2_g, norm2_b, x2);

    // 11. h = gelu(x2 @ w1 + b1)  (bf16 out)
    bfgemm<1,1><<<dim3(MLPH/128, Mrows/128), 256>>>(x2, w1b, b1, hb, Mrows, MLPH, Cdim, nullptr);

    // 12. out = xr + h @ w2 + b2  (fp32)
    bfgemm<2,0><<<dim3(Cdim/128, Mrows/128), 256>>>(hb, w2b, b2, out, Mrows, Cdim, MLPH, xr);
}